// round 1
// baseline (speedup 1.0000x reference)
#include <cuda_runtime.h>
#include <cstdint>
#include <cstddef>

// Problem constants
#define BB    4
#define CIN   256
#define HH    56
#define WW    56
#define COUT  256
#define KK9   9
#define OCH   18          // 2*OG*K*K offset channels
#define P     (HH*WW)     // 3136 pixels per image
#define NTOT  (BB*P)      // 12544
#define KDIM  (CIN*KK9)   // 2304

// cin chunking for offset conv partials
#define NCHUNK 8
#define CCH    (CIN/NCHUNK)   // 32

// Scratch (device globals: no allocations allowed)
__device__ __align__(16) float g_OffP[NCHUNK * BB * OCH * P];   // ~7.2 MB
__device__ __align__(16) float g_S[(size_t)KDIM * NTOT];        // ~115.6 MB

// ---------------------------------------------------------------------------
// Kernel 1: offset-predicting 3x3 conv, cin-chunked partial sums.
// grid: (ceil(P/256)=13, B, NCHUNK), block 256. Each thread = 1 pixel, 18 acc.
// ---------------------------------------------------------------------------
__global__ __launch_bounds__(256) void offconv_kernel(
    const float* __restrict__ x, const float* __restrict__ off_w,
    const float* __restrict__ off_b)
{
    __shared__ __align__(16) float ws[OCH * CCH * KK9];  // 5184 floats
    const int tid   = threadIdx.x;
    const int b     = blockIdx.y;
    const int chunk = blockIdx.z;
    const int ci0   = chunk * CCH;

    // stage weights for this cin chunk: ws[(oc*CCH+cl)*9+t]
    for (int i = tid; i < OCH * CCH * KK9; i += 256) {
        int oc  = i / (CCH * KK9);
        int rem = i % (CCH * KK9);
        int cl  = rem / KK9;
        int t   = rem % KK9;
        ws[i] = off_w[((size_t)(oc * CIN + ci0 + cl)) * KK9 + t];
    }
    __syncthreads();

    const int p = blockIdx.x * 256 + tid;
    if (p >= P) return;
    const int ho = p / WW;
    const int wo = p % WW;

    float acc[OCH];
#pragma unroll
    for (int oc = 0; oc < OCH; oc++)
        acc[oc] = (chunk == 0) ? off_b[oc] : 0.0f;

    const float* xb = x + ((size_t)(b * CIN + ci0)) * P;
    for (int cl = 0; cl < CCH; cl++) {
        const float* xc = xb + (size_t)cl * P;
        float v[KK9];
#pragma unroll
        for (int t = 0; t < KK9; t++) {
            int y  = ho + t / 3 - 1;
            int xx = wo + t % 3 - 1;
            v[t] = (y >= 0 && y < HH && xx >= 0 && xx < WW) ? xc[y * WW + xx] : 0.0f;
        }
#pragma unroll
        for (int t = 0; t < KK9; t++) {
#pragma unroll
            for (int oc = 0; oc < OCH; oc++)
                acc[oc] = fmaf(v[t], ws[(oc * CCH + cl) * KK9 + t], acc[oc]);
        }
    }

    float* op = g_OffP + (((size_t)chunk * BB + b) * OCH) * P;
#pragma unroll
    for (int oc = 0; oc < OCH; oc++)
        op[(size_t)oc * P + p] = acc[oc];
}

// ---------------------------------------------------------------------------
// Kernel 2: bilinear sampling -> S[(ci*9+kk)][b*P + p]
// grid: (13, B, 9), block 256. Each thread: one (b,kk,p); loops over ci.
// ---------------------------------------------------------------------------
__global__ __launch_bounds__(256) void sample_kernel(const float* __restrict__ x)
{
    const int tid = threadIdx.x;
    const int p   = blockIdx.x * 256 + tid;
    if (p >= P) return;
    const int b  = blockIdx.y;
    const int kk = blockIdx.z;

    // reduce offset partials
    float offy = 0.0f, offx = 0.0f;
#pragma unroll
    for (int c = 0; c < NCHUNK; c++) {
        const float* op = g_OffP + (((size_t)c * BB + b) * OCH + 2 * kk) * P + p;
        offy += op[0];
        offx += op[P];
    }

    const int ho = p / WW;
    const int wo = p % WW;
    const float py = (float)(ho - 1 + kk / 3) + offy;
    const float px = (float)(wo - 1 + kk % 3) + offx;
    const float fy = floorf(py), fx = floorf(px);
    const int y0 = (int)fy, x0 = (int)fx;
    const int y1 = y0 + 1,  x1 = x0 + 1;
    const float ty = py - fy, tx = px - fx;

    float w00 = (1.0f - ty) * (1.0f - tx);
    float w01 = (1.0f - ty) * tx;
    float w10 = ty * (1.0f - tx);
    float w11 = ty * tx;

    const bool vy0 = (y0 >= 0 && y0 < HH), vy1 = (y1 >= 0 && y1 < HH);
    const bool vx0 = (x0 >= 0 && x0 < WW), vx1 = (x1 >= 0 && x1 < WW);
    w00 *= (vy0 && vx0) ? 1.0f : 0.0f;
    w01 *= (vy0 && vx1) ? 1.0f : 0.0f;
    w10 *= (vy1 && vx0) ? 1.0f : 0.0f;
    w11 *= (vy1 && vx1) ? 1.0f : 0.0f;

    const int cy0 = min(max(y0, 0), HH - 1), cy1 = min(max(y1, 0), HH - 1);
    const int cx0 = min(max(x0, 0), WW - 1), cx1 = min(max(x1, 0), WW - 1);
    const int i00 = cy0 * WW + cx0, i01 = cy0 * WW + cx1;
    const int i10 = cy1 * WW + cx0, i11 = cy1 * WW + cx1;

    const float* xb = x + (size_t)b * CIN * P;
    float* sp = g_S + (size_t)kk * NTOT + (size_t)b * P + p;
    const size_t srow = (size_t)KK9 * NTOT;

#pragma unroll 4
    for (int ci = 0; ci < CIN; ci++) {
        const float* xc = xb + (size_t)ci * P;
        float v = w00 * __ldg(xc + i00) + w01 * __ldg(xc + i01)
                + w10 * __ldg(xc + i10) + w11 * __ldg(xc + i11);
        sp[(size_t)ci * srow] = v;
    }
}

// ---------------------------------------------------------------------------
// Kernel 3: SGEMM  out[co][n] = W[co][k] * S[k][n],  M=256, N=12544, K=2304
// 128x64x16 tiles, 256 threads, 8x4 micro-tile, double-buffered smem.
// Exact tiling: no bound checks anywhere. Output re-indexed to [b][co][p].
// ---------------------------------------------------------------------------
#define MT 128
#define NT 64
#define KT 16
#define NKC (KDIM / KT)   // 144

__global__ __launch_bounds__(256) void gemm_kernel(
    const float* __restrict__ Wm, float* __restrict__ out)
{
    __shared__ __align__(16) float As[2][KT][MT];
    __shared__ __align__(16) float Bs[2][KT][NT];

    const int tid   = threadIdx.x;
    const int n0    = blockIdx.x * NT;   // 0..195 tiles
    const int m0    = blockIdx.y * MT;   // 0..1 tiles

    // A staging: each thread loads 2 float4 of one weight row
    const int ar  = tid >> 1;            // 0..127 (row within M tile)
    const int akq = (tid & 1) * 8;       // k offset 0 or 8
    // B staging: each thread loads 1 float4
    const int bkr = tid >> 4;            // 0..15 (k row)
    const int bnq = (tid & 15) * 4;      // n offset

    const float* Ap = Wm + (size_t)(m0 + ar) * KDIM + akq;
    const float* Bp = g_S + (size_t)bkr * NTOT + n0 + bnq;

    const int ty = tid >> 4;   // 0..15 -> m micro (8 rows)
    const int tx = tid & 15;   // 0..15 -> n micro (4 cols)

    float acc[8][4];
#pragma unroll
    for (int i = 0; i < 8; i++)
#pragma unroll
        for (int j = 0; j < 4; j++) acc[i][j] = 0.0f;

    // preload chunk 0
    {
        float4 a0 = *(const float4*)Ap;
        float4 a1 = *(const float4*)(Ap + 4);
        float4 bv = *(const float4*)Bp;
        As[0][akq + 0][ar] = a0.x; As[0][akq + 1][ar] = a0.y;
        As[0][akq + 2][ar] = a0.z; As[0][akq + 3][ar] = a0.w;
        As[0][akq + 4][ar] = a1.x; As[0][akq + 5][ar] = a1.y;
        As[0][akq + 6][ar] = a1.z; As[0][akq + 7][ar] = a1.w;
        *(float4*)&Bs[0][bkr][bnq] = bv;
    }
    __syncthreads();

    int buf = 0;
    for (int kc = 0; kc < NKC; kc++) {
        float4 na0, na1, nbv;
        if (kc < NKC - 1) {
            const float* ap = Ap + (size_t)(kc + 1) * KT;
            na0 = *(const float4*)ap;
            na1 = *(const float4*)(ap + 4);
            nbv = *(const float4*)(Bp + (size_t)(kc + 1) * KT * NTOT);
        }
#pragma unroll
        for (int k2 = 0; k2 < KT; k2++) {
            float4 af0 = *(const float4*)&As[buf][k2][ty * 8];
            float4 af1 = *(const float4*)&As[buf][k2][ty * 8 + 4];
            float4 bf  = *(const float4*)&Bs[buf][k2][tx * 4];
            float a_[8] = {af0.x, af0.y, af0.z, af0.w, af1.x, af1.y, af1.z, af1.w};
            float b_[4] = {bf.x, bf.y, bf.z, bf.w};
#pragma unroll
            for (int i = 0; i < 8; i++)
#pragma unroll
                for (int j = 0; j < 4; j++)
                    acc[i][j] = fmaf(a_[i], b_[j], acc[i][j]);
        }
        if (kc < NKC - 1) {
            buf ^= 1;
            As[buf][akq + 0][ar] = na0.x; As[buf][akq + 1][ar] = na0.y;
            As[buf][akq + 2][ar] = na0.z; As[buf][akq + 3][ar] = na0.w;
            As[buf][akq + 4][ar] = na1.x; As[buf][akq + 5][ar] = na1.y;
            As[buf][akq + 6][ar] = na1.z; As[buf][akq + 7][ar] = na1.w;
            *(float4*)&Bs[buf][bkr][bnq] = nbv;
            __syncthreads();
        }
    }

    // epilogue: n tile lies fully within one batch (P % NT == 0)
    const int bidx = n0 / P;
    const int pofs = (n0 % P) + tx * 4;
    float* op = out + ((size_t)(bidx * COUT + m0 + ty * 8)) * P + pofs;
#pragma unroll
    for (int i = 0; i < 8; i++) {
        float4 v = make_float4(acc[i][0], acc[i][1], acc[i][2], acc[i][3]);
        *(float4*)(op + (size_t)i * P) = v;
    }
}

// ---------------------------------------------------------------------------
extern "C" void kernel_launch(void* const* d_in, const int* in_sizes, int n_in,
                              void* d_out, int out_size)
{
    const float* x     = (const float*)d_in[0];
    const float* wgt   = (const float*)d_in[1];
    const float* off_w = (const float*)d_in[2];
    const float* off_b = (const float*)d_in[3];
    float* out = (float*)d_out;

    dim3 g1((P + 255) / 256, BB, NCHUNK);
    offconv_kernel<<<g1, 256>>>(x, off_w, off_b);

    dim3 g2((P + 255) / 256, BB, KK9);
    sample_kernel<<<g2, 256>>>(x);

    dim3 g3(NTOT / NT, COUT / MT);
    gemm_kernel<<<g3, 256>>>(wgt, out);
}

// round 2
// speedup vs baseline: 1.0387x; 1.0387x over previous
#include <cuda_runtime.h>
#include <cstdint>
#include <cstddef>

// Problem constants
#define BB    4
#define CIN   256
#define HH    56
#define WW    56
#define COUT  256
#define KK9   9
#define OCH   18          // 2*OG*K*K offset channels
#define P     (HH*WW)     // 3136 pixels per image
#define NTOT  (BB*P)      // 12544
#define KDIM  (CIN*KK9)   // 2304

// cin chunking for offset conv partials
#define NCHUNK 16
#define CCH    (CIN/NCHUNK)   // 16

// Scratch (device globals: no allocations allowed)
__device__ __align__(16) float g_OffP[NCHUNK * BB * OCH * P];   // ~14.4 MB
__device__ __align__(16) float g_S[(size_t)KDIM * NTOT];        // ~115.6 MB

// ---------------------------------------------------------------------------
// packed f32x2 helpers (sm_103a FFMA2 — only reachable via PTX)
// ---------------------------------------------------------------------------
__device__ __forceinline__ void ffma2(uint64_t& d, uint64_t a, uint64_t b) {
    asm("fma.rn.f32x2 %0, %1, %2, %0;" : "+l"(d) : "l"(a), "l"(b));
}
__device__ __forceinline__ uint64_t splat2(float v) {
    uint64_t r;
    asm("mov.b64 %0, {%1, %1};" : "=l"(r) : "f"(v));
    return r;
}

// ---------------------------------------------------------------------------
// Kernel 1: offset-predicting 3x3 conv, cin-chunked partial sums.
// grid: (13, B, NCHUNK), block 256. Each thread = 1 pixel, 18 acc.
// ---------------------------------------------------------------------------
__global__ __launch_bounds__(256) void offconv_kernel(
    const float* __restrict__ x, const float* __restrict__ off_w,
    const float* __restrict__ off_b)
{
    __shared__ __align__(16) float ws[OCH * CCH * KK9];
    const int tid   = threadIdx.x;
    const int b     = blockIdx.y;
    const int chunk = blockIdx.z;
    const int ci0   = chunk * CCH;

    for (int i = tid; i < OCH * CCH * KK9; i += 256) {
        int oc  = i / (CCH * KK9);
        int rem = i % (CCH * KK9);
        int cl  = rem / KK9;
        int t   = rem % KK9;
        ws[i] = off_w[((size_t)(oc * CIN + ci0 + cl)) * KK9 + t];
    }
    __syncthreads();

    const int p = blockIdx.x * 256 + tid;
    if (p >= P) return;
    const int ho = p / WW;
    const int wo = p % WW;

    float acc[OCH];
#pragma unroll
    for (int oc = 0; oc < OCH; oc++)
        acc[oc] = (chunk == 0) ? off_b[oc] : 0.0f;

    const float* xb = x + ((size_t)(b * CIN + ci0)) * P;
    for (int cl = 0; cl < CCH; cl++) {
        const float* xc = xb + (size_t)cl * P;
        float v[KK9];
#pragma unroll
        for (int t = 0; t < KK9; t++) {
            int y  = ho + t / 3 - 1;
            int xx = wo + t % 3 - 1;
            v[t] = (y >= 0 && y < HH && xx >= 0 && xx < WW) ? xc[y * WW + xx] : 0.0f;
        }
#pragma unroll
        for (int t = 0; t < KK9; t++) {
#pragma unroll
            for (int oc = 0; oc < OCH; oc++)
                acc[oc] = fmaf(v[t], ws[(oc * CCH + cl) * KK9 + t], acc[oc]);
        }
    }

    float* op = g_OffP + (((size_t)chunk * BB + b) * OCH) * P;
#pragma unroll
    for (int oc = 0; oc < OCH; oc++)
        op[(size_t)oc * P + p] = acc[oc];
}

// ---------------------------------------------------------------------------
// Kernel 2: bilinear sampling -> S[(ci*9+kk)][b*P + p]
// ---------------------------------------------------------------------------
__global__ __launch_bounds__(256) void sample_kernel(const float* __restrict__ x)
{
    const int tid = threadIdx.x;
    const int p   = blockIdx.x * 256 + tid;
    if (p >= P) return;
    const int b  = blockIdx.y;
    const int kk = blockIdx.z;

    float offy = 0.0f, offx = 0.0f;
#pragma unroll
    for (int c = 0; c < NCHUNK; c++) {
        const float* op = g_OffP + (((size_t)c * BB + b) * OCH + 2 * kk) * P + p;
        offy += op[0];
        offx += op[P];
    }

    const int ho = p / WW;
    const int wo = p % WW;
    const float py = (float)(ho - 1 + kk / 3) + offy;
    const float px = (float)(wo - 1 + kk % 3) + offx;
    const float fy = floorf(py), fx = floorf(px);
    const int y0 = (int)fy, x0 = (int)fx;
    const int y1 = y0 + 1,  x1 = x0 + 1;
    const float ty = py - fy, tx = px - fx;

    float w00 = (1.0f - ty) * (1.0f - tx);
    float w01 = (1.0f - ty) * tx;
    float w10 = ty * (1.0f - tx);
    float w11 = ty * tx;

    const bool vy0 = (y0 >= 0 && y0 < HH), vy1 = (y1 >= 0 && y1 < HH);
    const bool vx0 = (x0 >= 0 && x0 < WW), vx1 = (x1 >= 0 && x1 < WW);
    w00 *= (vy0 && vx0) ? 1.0f : 0.0f;
    w01 *= (vy0 && vx1) ? 1.0f : 0.0f;
    w10 *= (vy1 && vx0) ? 1.0f : 0.0f;
    w11 *= (vy1 && vx1) ? 1.0f : 0.0f;

    const int cy0 = min(max(y0, 0), HH - 1), cy1 = min(max(y1, 0), HH - 1);
    const int cx0 = min(max(x0, 0), WW - 1), cx1 = min(max(x1, 0), WW - 1);
    const int i00 = cy0 * WW + cx0, i01 = cy0 * WW + cx1;
    const int i10 = cy1 * WW + cx0, i11 = cy1 * WW + cx1;

    const float* xb = x + (size_t)b * CIN * P;
    float* sp = g_S + (size_t)kk * NTOT + (size_t)b * P + p;
    const size_t srow = (size_t)KK9 * NTOT;

#pragma unroll 4
    for (int ci = 0; ci < CIN; ci++) {
        const float* xc = xb + (size_t)ci * P;
        float v = w00 * __ldg(xc + i00) + w01 * __ldg(xc + i01)
                + w10 * __ldg(xc + i10) + w11 * __ldg(xc + i11);
        sp[(size_t)ci * srow] = v;
    }
}

// ---------------------------------------------------------------------------
// Kernel 3: SGEMM via packed fma.rn.f32x2.
// out[co][n] = W[co][k] * S[k][n],  M=256, N=12544, K=2304
// 128x64x16 tiles, 256 threads, 8x4 micro-tile (acc packed in M pairs).
// ---------------------------------------------------------------------------
#define MT 128
#define NT 64
#define KT 16
#define NKC (KDIM / KT)   // 144

__global__ __launch_bounds__(256) void gemm_kernel(
    const float* __restrict__ Wm, float* __restrict__ out)
{
    __shared__ __align__(16) float As[2][KT][MT];
    __shared__ __align__(16) float Bs[2][KT][NT];

    const int tid = threadIdx.x;
    const int n0  = blockIdx.x * NT;
    const int m0  = blockIdx.y * MT;

    const int ar  = tid >> 1;
    const int akq = (tid & 1) * 8;
    const int bkr = tid >> 4;
    const int bnq = (tid & 15) * 4;

    const float* Ap = Wm + (size_t)(m0 + ar) * KDIM + akq;
    const float* Bp = g_S + (size_t)bkr * NTOT + n0 + bnq;

    const int ty = tid >> 4;   // 0..15 -> m micro (8 rows = 4 pairs)
    const int tx = tid & 15;   // 0..15 -> n micro (4 cols)

    uint64_t acc[4][4];        // [m-pair][n] packed f32x2
#pragma unroll
    for (int i = 0; i < 4; i++)
#pragma unroll
        for (int j = 0; j < 4; j++) acc[i][j] = 0ull;

    {
        float4 a0 = *(const float4*)Ap;
        float4 a1 = *(const float4*)(Ap + 4);
        float4 bv = *(const float4*)Bp;
        As[0][akq + 0][ar] = a0.x; As[0][akq + 1][ar] = a0.y;
        As[0][akq + 2][ar] = a0.z; As[0][akq + 3][ar] = a0.w;
        As[0][akq + 4][ar] = a1.x; As[0][akq + 5][ar] = a1.y;
        As[0][akq + 6][ar] = a1.z; As[0][akq + 7][ar] = a1.w;
        *(float4*)&Bs[0][bkr][bnq] = bv;
    }
    __syncthreads();

    int buf = 0;
    for (int kc = 0; kc < NKC; kc++) {
        float4 na0, na1, nbv;
        if (kc < NKC - 1) {
            const float* ap = Ap + (size_t)(kc + 1) * KT;
            na0 = *(const float4*)ap;
            na1 = *(const float4*)(ap + 4);
            nbv = *(const float4*)(Bp + (size_t)(kc + 1) * KT * NTOT);
        }
#pragma unroll
        for (int k2 = 0; k2 < KT; k2++) {
            // A pairs: (m, m+1) contiguous in As -> direct 64-bit packed loads
            ulonglong2 aa0 = *(const ulonglong2*)&As[buf][k2][ty * 8];
            ulonglong2 aa1 = *(const ulonglong2*)&As[buf][k2][ty * 8 + 4];
            uint64_t a_[4] = {aa0.x, aa0.y, aa1.x, aa1.y};
            float4 bf = *(const float4*)&Bs[buf][k2][tx * 4];
            uint64_t b_[4] = {splat2(bf.x), splat2(bf.y), splat2(bf.z), splat2(bf.w)};
#pragma unroll
            for (int i = 0; i < 4; i++)
#pragma unroll
                for (int j = 0; j < 4; j++)
                    ffma2(acc[i][j], a_[i], b_[j]);
        }
        if (kc < NKC - 1) {
            buf ^= 1;
            As[buf][akq + 0][ar] = na0.x; As[buf][akq + 1][ar] = na0.y;
            As[buf][akq + 2][ar] = na0.z; As[buf][akq + 3][ar] = na0.w;
            As[buf][akq + 4][ar] = na1.x; As[buf][akq + 5][ar] = na1.y;
            As[buf][akq + 6][ar] = na1.z; As[buf][akq + 7][ar] = na1.w;
            *(float4*)&Bs[buf][bkr][bnq] = nbv;
            __syncthreads();
        }
    }

    // epilogue: unpack m-pairs; n tile lies fully within one batch
    const int bidx = n0 / P;
    const int pofs = (n0 % P) + tx * 4;
    float* obase = out + ((size_t)(bidx * COUT + m0 + ty * 8)) * P + pofs;
#pragma unroll
    for (int i = 0; i < 4; i++) {
        float2 c0 = *(float2*)&acc[i][0];
        float2 c1 = *(float2*)&acc[i][1];
        float2 c2 = *(float2*)&acc[i][2];
        float2 c3 = *(float2*)&acc[i][3];
        float* r0 = obase + (size_t)(2 * i) * P;
        float* r1 = r0 + P;
        *(float4*)r0 = make_float4(c0.x, c1.x, c2.x, c3.x);
        *(float4*)r1 = make_float4(c0.y, c1.y, c2.y, c3.y);
    }
}

// ---------------------------------------------------------------------------
extern "C" void kernel_launch(void* const* d_in, const int* in_sizes, int n_in,
                              void* d_out, int out_size)
{
    const float* x     = (const float*)d_in[0];
    const float* wgt   = (const float*)d_in[1];
    const float* off_w = (const float*)d_in[2];
    const float* off_b = (const float*)d_in[3];
    float* out = (float*)d_out;

    dim3 g1((P + 255) / 256, BB, NCHUNK);
    offconv_kernel<<<g1, 256>>>(x, off_w, off_b);

    dim3 g2((P + 255) / 256, BB, KK9);
    sample_kernel<<<g2, 256>>>(x);

    dim3 g3(NTOT / NT, COUT / MT);
    gemm_kernel<<<g3, 256>>>(wgt, out);
}

// round 4
// speedup vs baseline: 1.7498x; 1.6845x over previous
#include <cuda_runtime.h>
#include <cuda_bf16.h>
#include <cstdint>
#include <cstddef>

// Problem constants
#define BB    4
#define CIN   256
#define HH    56
#define WW    56
#define COUT  256
#define KK9   9
#define OCH   18
#define P     (HH*WW)     // 3136
#define NTOT  (BB*P)      // 12544
#define KDIM  (CIN*KK9)   // 2304

#define NCHUNK 16
#define CCH    (CIN/NCHUNK)

// GEMM tiling
#define BM   128
#define BN   64
#define BK   32
#define NKC  (KDIM/BK)    // 72

// padded smem rows (bytes)
#define A_ROWB 80         // 32 bf16 = 64B data + 16B pad
#define B_ROWB 144        // 64 bf16 = 128B data + 16B pad
#define A_PLANE (BM*A_ROWB)          // 10240
#define B_PLANE (BK*B_ROWB)          // 4608
#define A_LO_OFF A_PLANE
#define B_HI_OFF (2*A_PLANE)         // 20480
#define B_LO_OFF (2*A_PLANE+B_PLANE) // 25088
#define BUF_BYTES (2*A_PLANE+2*B_PLANE)  // 29696
#define SMEM_TOTAL (2*BUF_BYTES)         // 59392

// Scratch (device globals)
__device__ __align__(16) float g_OffP[NCHUNK * BB * OCH * P];
__device__ __align__(16) __nv_bfloat16 g_Shi[(size_t)KDIM * NTOT];
__device__ __align__(16) __nv_bfloat16 g_Slo[(size_t)KDIM * NTOT];
__device__ __align__(16) __nv_bfloat16 g_Whi[COUT * KDIM];
__device__ __align__(16) __nv_bfloat16 g_Wlo[COUT * KDIM];

// ---------------------------------------------------------------------------
// helpers
// ---------------------------------------------------------------------------
__device__ __forceinline__ uint32_t smem_u32(const void* p) {
    uint32_t a;
    asm("{ .reg .u64 t; cvta.to.shared.u64 t, %1; cvt.u32.u64 %0, t; }" : "=r"(a) : "l"(p));
    return a;
}
__device__ __forceinline__ void cp16(uint32_t dst, const void* src) {
    asm volatile("cp.async.ca.shared.global [%0], [%1], 16;" :: "r"(dst), "l"(src) : "memory");
}
__device__ __forceinline__ void cp_commit() {
    asm volatile("cp.async.commit_group;" ::: "memory");
}
__device__ __forceinline__ void cp_wait1() {
    asm volatile("cp.async.wait_group 1;" ::: "memory");
}
__device__ __forceinline__ void cp_wait0() {
    asm volatile("cp.async.wait_group 0;" ::: "memory");
}
__device__ __forceinline__ void ldsm_x4(uint32_t* r, uint32_t addr) {
    asm volatile("ldmatrix.sync.aligned.m8n8.x4.shared.b16 {%0,%1,%2,%3}, [%4];"
                 : "=r"(r[0]), "=r"(r[1]), "=r"(r[2]), "=r"(r[3]) : "r"(addr));
}
__device__ __forceinline__ void ldsm_x4t(uint32_t* r, uint32_t addr) {
    asm volatile("ldmatrix.sync.aligned.m8n8.x4.trans.shared.b16 {%0,%1,%2,%3}, [%4];"
                 : "=r"(r[0]), "=r"(r[1]), "=r"(r[2]), "=r"(r[3]) : "r"(addr));
}
__device__ __forceinline__ void mma_bf16(float* c, const uint32_t* a, uint32_t b0, uint32_t b1) {
    asm volatile("mma.sync.aligned.m16n8k16.row.col.f32.bf16.bf16.f32 "
                 "{%0,%1,%2,%3}, {%4,%5,%6,%7}, {%8,%9}, {%0,%1,%2,%3};"
                 : "+f"(c[0]), "+f"(c[1]), "+f"(c[2]), "+f"(c[3])
                 : "r"(a[0]), "r"(a[1]), "r"(a[2]), "r"(a[3]), "r"(b0), "r"(b1));
}

// ---------------------------------------------------------------------------
// Kernel 0: weight -> bf16 hi/lo split
// ---------------------------------------------------------------------------
__global__ __launch_bounds__(256) void wconv_kernel(const float* __restrict__ w) {
    int i = blockIdx.x * 256 + threadIdx.x;
    if (i >= COUT * KDIM) return;
    float v = w[i];
    __nv_bfloat16 hi = __float2bfloat16_rn(v);
    __nv_bfloat16 lo = __float2bfloat16_rn(v - __bfloat162float(hi));
    g_Whi[i] = hi;
    g_Wlo[i] = lo;
}

// ---------------------------------------------------------------------------
// Kernel 1: offset-predicting 3x3 conv
// ---------------------------------------------------------------------------
__global__ __launch_bounds__(256) void offconv_kernel(
    const float* __restrict__ x, const float* __restrict__ off_w,
    const float* __restrict__ off_b)
{
    __shared__ __align__(16) float ws[OCH * CCH * KK9];
    const int tid   = threadIdx.x;
    const int b     = blockIdx.y;
    const int chunk = blockIdx.z;
    const int ci0   = chunk * CCH;

    for (int i = tid; i < OCH * CCH * KK9; i += 256) {
        int oc  = i / (CCH * KK9);
        int rem = i % (CCH * KK9);
        int cl  = rem / KK9;
        int t   = rem % KK9;
        ws[i] = off_w[((size_t)(oc * CIN + ci0 + cl)) * KK9 + t];
    }
    __syncthreads();

    const int p = blockIdx.x * 256 + tid;
    if (p >= P) return;
    const int ho = p / WW;
    const int wo = p % WW;

    float acc[OCH];
#pragma unroll
    for (int oc = 0; oc < OCH; oc++)
        acc[oc] = (chunk == 0) ? off_b[oc] : 0.0f;

    const float* xb = x + ((size_t)(b * CIN + ci0)) * P;
    for (int cl = 0; cl < CCH; cl++) {
        const float* xc = xb + (size_t)cl * P;
        float v[KK9];
#pragma unroll
        for (int t = 0; t < KK9; t++) {
            int y  = ho + t / 3 - 1;
            int xx = wo + t % 3 - 1;
            v[t] = (y >= 0 && y < HH && xx >= 0 && xx < WW) ? xc[y * WW + xx] : 0.0f;
        }
#pragma unroll
        for (int t = 0; t < KK9; t++) {
#pragma unroll
            for (int oc = 0; oc < OCH; oc++)
                acc[oc] = fmaf(v[t], ws[(oc * CCH + cl) * KK9 + t], acc[oc]);
        }
    }

    float* op = g_OffP + (((size_t)chunk * BB + b) * OCH) * P;
#pragma unroll
    for (int oc = 0; oc < OCH; oc++)
        op[(size_t)oc * P + p] = acc[oc];
}

// ---------------------------------------------------------------------------
// Kernel 2: bilinear sampling -> S hi/lo bf16, layout [k=ci*9+kk][n=b*P+p]
// ---------------------------------------------------------------------------
__global__ __launch_bounds__(256) void sample_kernel(const float* __restrict__ x)
{
    const int tid = threadIdx.x;
    const int p   = blockIdx.x * 256 + tid;
    if (p >= P) return;
    const int b  = blockIdx.y;
    const int kk = blockIdx.z;

    float offy = 0.0f, offx = 0.0f;
#pragma unroll
    for (int c = 0; c < NCHUNK; c++) {
        const float* op = g_OffP + (((size_t)c * BB + b) * OCH + 2 * kk) * P + p;
        offy += op[0];
        offx += op[P];
    }

    const int ho = p / WW;
    const int wo = p % WW;
    const float py = (float)(ho - 1 + kk / 3) + offy;
    const float px = (float)(wo - 1 + kk % 3) + offx;
    const float fy = floorf(py), fx = floorf(px);
    const int y0 = (int)fy, x0 = (int)fx;
    const int y1 = y0 + 1,  x1 = x0 + 1;
    const float ty = py - fy, tx = px - fx;

    float w00 = (1.0f - ty) * (1.0f - tx);
    float w01 = (1.0f - ty) * tx;
    float w10 = ty * (1.0f - tx);
    float w11 = ty * tx;

    const bool vy0 = (y0 >= 0 && y0 < HH), vy1 = (y1 >= 0 && y1 < HH);
    const bool vx0 = (x0 >= 0 && x0 < WW), vx1 = (x1 >= 0 && x1 < WW);
    w00 *= (vy0 && vx0) ? 1.0f : 0.0f;
    w01 *= (vy0 && vx1) ? 1.0f : 0.0f;
    w10 *= (vy1 && vx0) ? 1.0f : 0.0f;
    w11 *= (vy1 && vx1) ? 1.0f : 0.0f;

    const int cy0 = min(max(y0, 0), HH - 1), cy1 = min(max(y1, 0), HH - 1);
    const int cx0 = min(max(x0, 0), WW - 1), cx1 = min(max(x1, 0), WW - 1);
    const int i00 = cy0 * WW + cx0, i01 = cy0 * WW + cx1;
    const int i10 = cy1 * WW + cx0, i11 = cy1 * WW + cx1;

    const float* xb = x + (size_t)b * CIN * P;
    const size_t base = (size_t)kk * NTOT + (size_t)b * P + p;
    const size_t srow = (size_t)KK9 * NTOT;

#pragma unroll 4
    for (int ci = 0; ci < CIN; ci++) {
        const float* xc = xb + (size_t)ci * P;
        float v = w00 * __ldg(xc + i00) + w01 * __ldg(xc + i01)
                + w10 * __ldg(xc + i10) + w11 * __ldg(xc + i11);
        __nv_bfloat16 hi = __float2bfloat16_rn(v);
        __nv_bfloat16 lo = __float2bfloat16_rn(v - __bfloat162float(hi));
        g_Shi[base + (size_t)ci * srow] = hi;
        g_Slo[base + (size_t)ci * srow] = lo;
    }
}

// ---------------------------------------------------------------------------
// Kernel 3: mma.sync bf16-split GEMM. out[co][n] = W[co][k]*S[k][n]
// BM=128, BN=64, BK=32. 8 warps: 4(M) x 2(N), warp tile 32x32.
// D = Wh*Sh + Wh*Sl + Wl*Sh, fp32 accum.
// ---------------------------------------------------------------------------
__device__ __forceinline__ void prefetch_chunk(uint32_t sbase, int tid,
                                               int m0, int n0, int k0)
{
    // A: 2 planes x 128 rows x 4 chunks of 16B
#pragma unroll
    for (int it = 0; it < 2; it++) {
        int idx = it * 256 + tid;       // 0..511
        int row = idx >> 2;
        int c   = idx & 3;
        const __nv_bfloat16* srch = g_Whi + (size_t)(m0 + row) * KDIM + k0 + c * 8;
        const __nv_bfloat16* srcl = g_Wlo + (size_t)(m0 + row) * KDIM + k0 + c * 8;
        uint32_t d = row * A_ROWB + c * 16;
        cp16(sbase + d, srch);
        cp16(sbase + A_LO_OFF + d, srcl);
    }
    // B: 2 planes x 32 rows x 8 chunks of 16B
    {
        int row = tid >> 3;
        int c   = tid & 7;
        const __nv_bfloat16* srch = g_Shi + (size_t)(k0 + row) * NTOT + n0 + c * 8;
        const __nv_bfloat16* srcl = g_Slo + (size_t)(k0 + row) * NTOT + n0 + c * 8;
        uint32_t d = row * B_ROWB + c * 16;
        cp16(sbase + B_HI_OFF + d, srch);
        cp16(sbase + B_LO_OFF + d, srcl);
    }
}

__global__ __launch_bounds__(256) void gemm_mma_kernel(float* __restrict__ out)
{
    extern __shared__ char smem[];
    const uint32_t sb = smem_u32(smem);
    const int tid  = threadIdx.x;
    const int wid  = tid >> 5;
    const int lane = tid & 31;
    const int wm   = wid & 3;      // 0..3 -> M
    const int wn   = wid >> 2;     // 0..1 -> N
    const int n0   = blockIdx.x * BN;
    const int m0   = blockIdx.y * BM;

    float acc[2][4][4];
#pragma unroll
    for (int i = 0; i < 2; i++)
#pragma unroll
        for (int j = 0; j < 4; j++)
#pragma unroll
            for (int q = 0; q < 4; q++) acc[i][j][q] = 0.0f;

    // ldmatrix per-thread address components
    const int lrow = lane & 15;
    const int lhalf = lane >> 4;   // 0/1 -> +8 cols (x4: matrices 2,3)
    // A: addr = row*A_ROWB + (kk*16 + lhalf*8)*2 ; row = wm*32 + mt*16 + lrow
    const uint32_t a_row_off = (uint32_t)(wm * 32 + lrow) * A_ROWB + lhalf * 16;
    // B: addr = (kk*16 + lrow)*B_ROWB + (wn*32 + bq*16 + lhalf*8)*2
    const uint32_t b_off = (uint32_t)lrow * B_ROWB + (uint32_t)(wn * 32 + lhalf * 8) * 2;

    prefetch_chunk(sb, tid, m0, n0, 0);
    cp_commit();

    for (int kc = 0; kc < NKC; kc++) {
        const uint32_t buf = sb + (uint32_t)(kc & 1) * BUF_BYTES;
        if (kc < NKC - 1) {
            prefetch_chunk(sb + (uint32_t)((kc + 1) & 1) * BUF_BYTES, tid, m0, n0, (kc + 1) * BK);
            cp_commit();
            cp_wait1();
        } else {
            cp_wait0();
        }
        __syncthreads();

#pragma unroll
        for (int kk = 0; kk < 2; kk++) {
            uint32_t Ah[2][4], Al[2][4], Bh[2][4], Bl[2][4];
#pragma unroll
            for (int mt = 0; mt < 2; mt++) {
                uint32_t aaddr = buf + a_row_off + (uint32_t)mt * 16 * A_ROWB + kk * 32;
                ldsm_x4(Ah[mt], aaddr);
                ldsm_x4(Al[mt], aaddr + A_LO_OFF);
            }
#pragma unroll
            for (int bq = 0; bq < 2; bq++) {
                uint32_t baddr = buf + B_HI_OFF + b_off + (uint32_t)kk * 16 * B_ROWB + bq * 32;
                ldsm_x4t(Bh[bq], baddr);
                ldsm_x4t(Bl[bq], baddr + (B_LO_OFF - B_HI_OFF));
            }
            // three plane combos
#pragma unroll
            for (int mt = 0; mt < 2; mt++) {
#pragma unroll
                for (int bq = 0; bq < 2; bq++) {
#pragma unroll
                    for (int h = 0; h < 2; h++) {
                        int nt = bq * 2 + h;
                        mma_bf16(acc[mt][nt], Ah[mt], Bh[bq][2*h], Bh[bq][2*h+1]);
                        mma_bf16(acc[mt][nt], Ah[mt], Bl[bq][2*h], Bl[bq][2*h+1]);
                        mma_bf16(acc[mt][nt], Al[mt], Bh[bq][2*h], Bh[bq][2*h+1]);
                    }
                }
            }
        }
        __syncthreads();
    }

    // epilogue: C frag mapping (m16n8): c0=C[g][2t], c1=C[g][2t+1], c2=C[g+8][2t], c3=..
    const int g = lane >> 2;
    const int t = lane & 3;
    const int bidx = n0 / P;
    const int pofs = n0 % P;
#pragma unroll
    for (int mt = 0; mt < 2; mt++) {
        int mrow = m0 + wm * 32 + mt * 16 + g;
        float* r0 = out + ((size_t)(bidx * COUT + mrow)) * P + pofs;
        float* r1 = r0 + 8 * P;
#pragma unroll
        for (int nt = 0; nt < 4; nt++) {
            int col = wn * 32 + nt * 8 + 2 * t;
            *(float2*)(r0 + col) = make_float2(acc[mt][nt][0], acc[mt][nt][1]);
            *(float2*)(r1 + col) = make_float2(acc[mt][nt][2], acc[mt][nt][3]);
        }
    }
}

// ---------------------------------------------------------------------------
extern "C" void kernel_launch(void* const* d_in, const int* in_sizes, int n_in,
                              void* d_out, int out_size)
{
    const float* x     = (const float*)d_in[0];
    const float* wgt   = (const float*)d_in[1];
    const float* off_w = (const float*)d_in[2];
    const float* off_b = (const float*)d_in[3];
    float* out = (float*)d_out;

    cudaFuncSetAttribute(gemm_mma_kernel, cudaFuncAttributeMaxDynamicSharedMemorySize, SMEM_TOTAL);

    wconv_kernel<<<(COUT * KDIM + 255) / 256, 256>>>(wgt);

    dim3 g1((P + 255) / 256, BB, NCHUNK);
    offconv_kernel<<<g1, 256>>>(x, off_w, off_b);

    dim3 g2((P + 255) / 256, BB, KK9);
    sample_kernel<<<g2, 256>>>(x);

    dim3 g3(NTOT / BN, COUT / BM);
    gemm_mma_kernel<<<g3, 256, SMEM_TOTAL>>>(out);
}

// round 5
// speedup vs baseline: 1.8847x; 1.0771x over previous
#include <cuda_runtime.h>
#include <cuda_bf16.h>
#include <cstdint>
#include <cstddef>

// Problem constants
#define BB    4
#define CIN   256
#define HH    56
#define WW    56
#define COUT  256
#define KK9   9
#define OCH   18
#define P     (HH*WW)     // 3136
#define NTOT  (BB*P)      // 12544
#define KDIM  (CIN*KK9)   // 2304

#define NCHUNK 16
#define CCH    (CIN/NCHUNK)   // 16

// GEMM tiling
#define BM   128
#define BN   64
#define BK   32
#define NKC  (KDIM/BK)    // 72
#define NSTAGE 3

// padded smem rows (bytes)
#define A_ROWB 80
#define B_ROWB 144
#define A_PLANE (BM*A_ROWB)
#define B_PLANE (BK*B_ROWB)
#define A_LO_OFF A_PLANE
#define B_HI_OFF (2*A_PLANE)
#define B_LO_OFF (2*A_PLANE+B_PLANE)
#define BUF_BYTES (2*A_PLANE+2*B_PLANE)   // 29696
#define SMEM_TOTAL (NSTAGE*BUF_BYTES)     // 89088

// offconv strips
#define SY_N  (HH/4)          // 14 strips of 4 rows
#define STRIPS (BB*SY_N*WW)   // 3136

// Scratch (device globals)
__device__ __align__(16) float g_OffP[NCHUNK * BB * OCH * P];
__device__ __align__(16) __nv_bfloat16 g_Shi[(size_t)KDIM * NTOT];
__device__ __align__(16) __nv_bfloat16 g_Slo[(size_t)KDIM * NTOT];
__device__ __align__(16) __nv_bfloat16 g_Whi[COUT * KDIM];
__device__ __align__(16) __nv_bfloat16 g_Wlo[COUT * KDIM];

// ---------------------------------------------------------------------------
// helpers
// ---------------------------------------------------------------------------
__device__ __forceinline__ uint32_t smem_u32(const void* p) {
    uint32_t a;
    asm("{ .reg .u64 t; cvta.to.shared.u64 t, %1; cvt.u32.u64 %0, t; }" : "=r"(a) : "l"(p));
    return a;
}
__device__ __forceinline__ void cp16(uint32_t dst, const void* src) {
    asm volatile("cp.async.ca.shared.global [%0], [%1], 16;" :: "r"(dst), "l"(src) : "memory");
}
__device__ __forceinline__ void cp_commit() {
    asm volatile("cp.async.commit_group;" ::: "memory");
}
__device__ __forceinline__ void cp_wait1() {
    asm volatile("cp.async.wait_group 1;" ::: "memory");
}
__device__ __forceinline__ void ldsm_x4(uint32_t* r, uint32_t addr) {
    asm volatile("ldmatrix.sync.aligned.m8n8.x4.shared.b16 {%0,%1,%2,%3}, [%4];"
                 : "=r"(r[0]), "=r"(r[1]), "=r"(r[2]), "=r"(r[3]) : "r"(addr));
}
__device__ __forceinline__ void ldsm_x4t(uint32_t* r, uint32_t addr) {
    asm volatile("ldmatrix.sync.aligned.m8n8.x4.trans.shared.b16 {%0,%1,%2,%3}, [%4];"
                 : "=r"(r[0]), "=r"(r[1]), "=r"(r[2]), "=r"(r[3]) : "r"(addr));
}
__device__ __forceinline__ void mma_bf16(float* c, const uint32_t* a, uint32_t b0, uint32_t b1) {
    asm volatile("mma.sync.aligned.m16n8k16.row.col.f32.bf16.bf16.f32 "
                 "{%0,%1,%2,%3}, {%4,%5,%6,%7}, {%8,%9}, {%0,%1,%2,%3};"
                 : "+f"(c[0]), "+f"(c[1]), "+f"(c[2]), "+f"(c[3])
                 : "r"(a[0]), "r"(a[1]), "r"(a[2]), "r"(a[3]), "r"(b0), "r"(b1));
}

// ---------------------------------------------------------------------------
// Kernel 0: weight -> bf16 hi/lo split
// ---------------------------------------------------------------------------
__global__ __launch_bounds__(256) void wconv_kernel(const float* __restrict__ w) {
    int i = blockIdx.x * 256 + threadIdx.x;
    if (i >= COUT * KDIM) return;
    float v = w[i];
    __nv_bfloat16 hi = __float2bfloat16_rn(v);
    __nv_bfloat16 lo = __float2bfloat16_rn(v - __bfloat162float(hi));
    g_Whi[i] = hi;
    g_Wlo[i] = lo;
}

// ---------------------------------------------------------------------------
// Kernel 1: offset conv, strip version. Each thread: 1 column x 4 rows.
// Weights amortized over 4 pixels; patch loads 18/channel (4.5/pixel).
// grid: (ceil(STRIPS/256), NCHUNK)
// ---------------------------------------------------------------------------
__global__ __launch_bounds__(256) void offconv_kernel(
    const float* __restrict__ x, const float* __restrict__ off_w,
    const float* __restrict__ off_b)
{
    __shared__ __align__(16) float ws[OCH * CCH * KK9];
    const int tid   = threadIdx.x;
    const int chunk = blockIdx.y;
    const int ci0   = chunk * CCH;

    for (int i = tid; i < OCH * CCH * KK9; i += 256) {
        int oc  = i / (CCH * KK9);
        int rem = i % (CCH * KK9);
        int cl  = rem / KK9;
        int t   = rem % KK9;
        ws[i] = off_w[((size_t)(oc * CIN + ci0 + cl)) * KK9 + t];
    }
    __syncthreads();

    const int id = blockIdx.x * 256 + tid;
    if (id >= STRIPS) return;
    const int b   = id / (SY_N * WW);
    const int s   = id % (SY_N * WW);
    const int sy  = s / WW;
    const int sx  = s % WW;
    const int y0r = sy * 4;

    float acc[OCH][4];
#pragma unroll
    for (int oc = 0; oc < OCH; oc++) {
        float bias = (chunk == 0) ? off_b[oc] : 0.0f;
#pragma unroll
        for (int r = 0; r < 4; r++) acc[oc][r] = bias;
    }

    const float* xb = x + ((size_t)(b * CIN + ci0)) * P;
    for (int cl = 0; cl < CCH; cl++) {
        const float* xc = xb + (size_t)cl * P;
        float v[6][3];
#pragma unroll
        for (int dy = 0; dy < 6; dy++) {
            int y = y0r - 1 + dy;
#pragma unroll
            for (int dx = 0; dx < 3; dx++) {
                int xx = sx - 1 + dx;
                v[dy][dx] = (y >= 0 && y < HH && xx >= 0 && xx < WW)
                          ? xc[y * WW + xx] : 0.0f;
            }
        }
        const float* wsc = ws + cl * KK9;
#pragma unroll
        for (int oc = 0; oc < OCH; oc++) {
            const float* wo = wsc + oc * (CCH * KK9);
#pragma unroll
            for (int t = 0; t < KK9; t++) {
                float w = wo[t];
                int ty = t / 3, tx = t % 3;
#pragma unroll
                for (int r = 0; r < 4; r++)
                    acc[oc][r] = fmaf(v[r + ty][tx], w, acc[oc][r]);
            }
        }
    }

    float* op = g_OffP + (((size_t)chunk * BB + b) * OCH) * P;
#pragma unroll
    for (int oc = 0; oc < OCH; oc++) {
#pragma unroll
        for (int r = 0; r < 4; r++)
            op[(size_t)oc * P + (y0r + r) * WW + sx] = acc[oc][r];
    }
}

// ---------------------------------------------------------------------------
// Kernel 2: bilinear sampling -> S hi/lo bf16, layout [k=ci*9+kk][n=b*P+p]
// ---------------------------------------------------------------------------
__global__ __launch_bounds__(256) void sample_kernel(const float* __restrict__ x)
{
    const int tid = threadIdx.x;
    const int p   = blockIdx.x * 256 + tid;
    if (p >= P) return;
    const int b  = blockIdx.y;
    const int kk = blockIdx.z;

    float offy = 0.0f, offx = 0.0f;
#pragma unroll
    for (int c = 0; c < NCHUNK; c++) {
        const float* op = g_OffP + (((size_t)c * BB + b) * OCH + 2 * kk) * P + p;
        offy += op[0];
        offx += op[P];
    }

    const int ho = p / WW;
    const int wo = p % WW;
    const float py = (float)(ho - 1 + kk / 3) + offy;
    const float px = (float)(wo - 1 + kk % 3) + offx;
    const float fy = floorf(py), fx = floorf(px);
    const int y0 = (int)fy, x0 = (int)fx;
    const int y1 = y0 + 1,  x1 = x0 + 1;
    const float ty = py - fy, tx = px - fx;

    float w00 = (1.0f - ty) * (1.0f - tx);
    float w01 = (1.0f - ty) * tx;
    float w10 = ty * (1.0f - tx);
    float w11 = ty * tx;

    const bool vy0 = (y0 >= 0 && y0 < HH), vy1 = (y1 >= 0 && y1 < HH);
    const bool vx0 = (x0 >= 0 && x0 < WW), vx1 = (x1 >= 0 && x1 < WW);
    w00 *= (vy0 && vx0) ? 1.0f : 0.0f;
    w01 *= (vy0 && vx1) ? 1.0f : 0.0f;
    w10 *= (vy1 && vx0) ? 1.0f : 0.0f;
    w11 *= (vy1 && vx1) ? 1.0f : 0.0f;

    const int cy0 = min(max(y0, 0), HH - 1), cy1 = min(max(y1, 0), HH - 1);
    const int cx0 = min(max(x0, 0), WW - 1), cx1 = min(max(x1, 0), WW - 1);
    const int i00 = cy0 * WW + cx0, i01 = cy0 * WW + cx1;
    const int i10 = cy1 * WW + cx0, i11 = cy1 * WW + cx1;

    const float* xb = x + (size_t)b * CIN * P;
    const size_t base = (size_t)kk * NTOT + (size_t)b * P + p;
    const size_t srow = (size_t)KK9 * NTOT;

#pragma unroll 4
    for (int ci = 0; ci < CIN; ci++) {
        const float* xc = xb + (size_t)ci * P;
        float v = w00 * __ldg(xc + i00) + w01 * __ldg(xc + i01)
                + w10 * __ldg(xc + i10) + w11 * __ldg(xc + i11);
        __nv_bfloat16 hi = __float2bfloat16_rn(v);
        __nv_bfloat16 lo = __float2bfloat16_rn(v - __bfloat162float(hi));
        g_Shi[base + (size_t)ci * srow] = hi;
        g_Slo[base + (size_t)ci * srow] = lo;
    }
}

// ---------------------------------------------------------------------------
// Kernel 3: mma.sync bf16-split GEMM, 3-stage cp.async pipeline.
// ---------------------------------------------------------------------------
__device__ __forceinline__ void prefetch_chunk(uint32_t sbase, int tid,
                                               int m0, int n0, int k0)
{
#pragma unroll
    for (int it = 0; it < 2; it++) {
        int idx = it * 256 + tid;
        int row = idx >> 2;
        int c   = idx & 3;
        const __nv_bfloat16* srch = g_Whi + (size_t)(m0 + row) * KDIM + k0 + c * 8;
        const __nv_bfloat16* srcl = g_Wlo + (size_t)(m0 + row) * KDIM + k0 + c * 8;
        uint32_t d = row * A_ROWB + c * 16;
        cp16(sbase + d, srch);
        cp16(sbase + A_LO_OFF + d, srcl);
    }
    {
        int row = tid >> 3;
        int c   = tid & 7;
        const __nv_bfloat16* srch = g_Shi + (size_t)(k0 + row) * NTOT + n0 + c * 8;
        const __nv_bfloat16* srcl = g_Slo + (size_t)(k0 + row) * NTOT + n0 + c * 8;
        uint32_t d = row * B_ROWB + c * 16;
        cp16(sbase + B_HI_OFF + d, srch);
        cp16(sbase + B_LO_OFF + d, srcl);
    }
}

__global__ __launch_bounds__(256) void gemm_mma_kernel(float* __restrict__ out)
{
    extern __shared__ char smem[];
    const uint32_t sb = smem_u32(smem);
    const int tid  = threadIdx.x;
    const int wid  = tid >> 5;
    const int lane = tid & 31;
    const int wm   = wid & 3;
    const int wn   = wid >> 2;
    const int n0   = blockIdx.x * BN;
    const int m0   = blockIdx.y * BM;

    float acc[2][4][4];
#pragma unroll
    for (int i = 0; i < 2; i++)
#pragma unroll
        for (int j = 0; j < 4; j++)
#pragma unroll
            for (int q = 0; q < 4; q++) acc[i][j][q] = 0.0f;

    const int lrow = lane & 15;
    const int lhalf = lane >> 4;
    const uint32_t a_row_off = (uint32_t)(wm * 32 + lrow) * A_ROWB + lhalf * 16;
    const uint32_t b_off = (uint32_t)lrow * B_ROWB + (uint32_t)(wn * 32 + lhalf * 8) * 2;

    prefetch_chunk(sb, tid, m0, n0, 0);
    cp_commit();
    prefetch_chunk(sb + BUF_BYTES, tid, m0, n0, BK);
    cp_commit();

    for (int kc = 0; kc < NKC; kc++) {
        cp_wait1();              // chunk kc complete
        __syncthreads();         // all warps done computing chunk kc-1
        if (kc + 2 < NKC)
            prefetch_chunk(sb + (uint32_t)((kc + 2) % NSTAGE) * BUF_BYTES,
                           tid, m0, n0, (kc + 2) * BK);
        cp_commit();             // (possibly empty) group keeps count aligned

        const uint32_t buf = sb + (uint32_t)(kc % NSTAGE) * BUF_BYTES;
#pragma unroll
        for (int kk = 0; kk < 2; kk++) {
            uint32_t Ah[2][4], Al[2][4], Bh[2][4], Bl[2][4];
#pragma unroll
            for (int mt = 0; mt < 2; mt++) {
                uint32_t aaddr = buf + a_row_off + (uint32_t)mt * 16 * A_ROWB + kk * 32;
                ldsm_x4(Ah[mt], aaddr);
                ldsm_x4(Al[mt], aaddr + A_LO_OFF);
            }
#pragma unroll
            for (int bq = 0; bq < 2; bq++) {
                uint32_t baddr = buf + B_HI_OFF + b_off + (uint32_t)kk * 16 * B_ROWB + bq * 32;
                ldsm_x4t(Bh[bq], baddr);
                ldsm_x4t(Bl[bq], baddr + (B_LO_OFF - B_HI_OFF));
            }
#pragma unroll
            for (int mt = 0; mt < 2; mt++) {
#pragma unroll
                for (int bq = 0; bq < 2; bq++) {
#pragma unroll
                    for (int h = 0; h < 2; h++) {
                        int nt = bq * 2 + h;
                        mma_bf16(acc[mt][nt], Ah[mt], Bh[bq][2*h], Bh[bq][2*h+1]);
                        mma_bf16(acc[mt][nt], Ah[mt], Bl[bq][2*h], Bl[bq][2*h+1]);
                        mma_bf16(acc[mt][nt], Al[mt], Bh[bq][2*h], Bh[bq][2*h+1]);
                    }
                }
            }
        }
    }

    const int g = lane >> 2;
    const int t = lane & 3;
    const int bidx = n0 / P;
    const int pofs = n0 % P;
#pragma unroll
    for (int mt = 0; mt < 2; mt++) {
        int mrow = m0 + wm * 32 + mt * 16 + g;
        float* r0 = out + ((size_t)(bidx * COUT + mrow)) * P + pofs;
        float* r1 = r0 + 8 * P;
#pragma unroll
        for (int nt = 0; nt < 4; nt++) {
            int col = wn * 32 + nt * 8 + 2 * t;
            *(float2*)(r0 + col) = make_float2(acc[mt][nt][0], acc[mt][nt][1]);
            *(float2*)(r1 + col) = make_float2(acc[mt][nt][2], acc[mt][nt][3]);
        }
    }
}

// ---------------------------------------------------------------------------
extern "C" void kernel_launch(void* const* d_in, const int* in_sizes, int n_in,
                              void* d_out, int out_size)
{
    const float* x     = (const float*)d_in[0];
    const float* wgt   = (const float*)d_in[1];
    const float* off_w = (const float*)d_in[2];
    const float* off_b = (const float*)d_in[3];
    float* out = (float*)d_out;

    cudaFuncSetAttribute(gemm_mma_kernel, cudaFuncAttributeMaxDynamicSharedMemorySize, SMEM_TOTAL);

    wconv_kernel<<<(COUT * KDIM + 255) / 256, 256>>>(wgt);

    dim3 g1((STRIPS + 255) / 256, NCHUNK);
    offconv_kernel<<<g1, 256>>>(x, off_w, off_b);

    dim3 g2((P + 255) / 256, BB, KK9);
    sample_kernel<<<g2, 256>>>(x);

    dim3 g3(NTOT / BN, COUT / BM);
    gemm_mma_kernel<<<g3, 256, SMEM_TOTAL>>>(out);
}